// round 1
// baseline (speedup 1.0000x reference)
#include <cuda_runtime.h>
#include <cuda_bf16.h>

// Problem shape (validated against in_sizes at launch).
#define BMAX 16384
#define DDIM 128
#define SQ_STRIDE 132   // smem pitch in floats: 16B-aligned, bank-conflict-free with strided c/r maps

__device__ float g_pos[BMAX];     // diag(Q @ D^T) == pairwise pos scores
__device__ float g_term1[BMAX];   // softplus(neg - pos) per row
__device__ float g_rowmax[BMAX];  // max over cols of (Q @ D^T - BIG*eye)

__device__ __forceinline__ float softplusf(float x) {
    // stable softplus
    return x > 20.0f ? x : log1pf(__expf(x));
}

__device__ __forceinline__ void ffma2(unsigned long long& d,
                                      unsigned long long a,
                                      unsigned long long b) {
    // packed f32x2 FMA: 2 FMAs per instruction (sm_100+ / PTX only)
    asm("fma.rn.f32x2 %0, %1, %2, %0;" : "+l"(d) : "l"(a), "l"(b));
}

// ---------------------------------------------------------------------------
// Kernel A: per-row pairwise dots. One warp per row, float4 per lane.
// ---------------------------------------------------------------------------
__global__ void pairwise_kernel(const float* __restrict__ q,
                                const float* __restrict__ d,
                                const float* __restrict__ nd,
                                int B) {
    int warp = (blockIdx.x * blockDim.x + threadIdx.x) >> 5;
    int lane = threadIdx.x & 31;
    if (warp >= B) return;

    const float4 qv = *(const float4*)(q  + (size_t)warp * DDIM + lane * 4);
    const float4 dv = *(const float4*)(d  + (size_t)warp * DDIM + lane * 4);
    const float4 nv = *(const float4*)(nd + (size_t)warp * DDIM + lane * 4);

    float pos = qv.x * dv.x + qv.y * dv.y + qv.z * dv.z + qv.w * dv.w;
    float neg = qv.x * nv.x + qv.y * nv.y + qv.z * nv.z + qv.w * nv.w;

    #pragma unroll
    for (int off = 16; off > 0; off >>= 1) {
        pos += __shfl_xor_sync(0xFFFFFFFFu, pos, off);
        neg += __shfl_xor_sync(0xFFFFFFFFu, neg, off);
    }
    if (lane == 0) {
        g_pos[warp]   = pos;
        g_term1[warp] = softplusf(neg - pos);
    }
}

// ---------------------------------------------------------------------------
// Kernel B: fused max-GEMM. 128 rows per CTA; Q-tile resident in smem; sweep
// doc rows in 64-col chunks. 4x8 register microtile with packed f32x2 accums.
// Thread (tx=tid&7, ty=tid>>3) owns rows {ty + 32*i} and cols {tx + 8*j}.
// ---------------------------------------------------------------------------
__global__ void __launch_bounds__(256, 1)
inbatch_kernel(const float* __restrict__ Q, const float* __restrict__ Dm, int B) {
    extern __shared__ float smem[];
    float* Qs = smem;                        // 128 x SQ_STRIDE
    float* Ds = smem + 128 * SQ_STRIDE;      // 64  x SQ_STRIDE

    const int tid = threadIdx.x;
    const int tx = tid & 7;
    const int ty = tid >> 3;
    const int rowBase = blockIdx.x * 128;

    // Load Q tile (coalesced; row-major into pitched smem)
    #pragma unroll
    for (int i = 0; i < 16; ++i) {
        int e  = tid + 256 * i;            // float4 index, 0..4095
        int r  = e >> 5;                   // 32 float4 per row
        int kc = e & 31;
        float4 v = *(const float4*)(Q + (size_t)(rowBase + r) * DDIM + kc * 4);
        *(float4*)(Qs + r * SQ_STRIDE + kc * 4) = v;
    }

    int ri[4];
    float rmax[4];
    #pragma unroll
    for (int i = 0; i < 4; ++i) {
        ri[i]   = rowBase + ty + 32 * i;
        rmax[i] = -3.0e38f;
    }

    const int nChunks = B / 64;
    for (int chunk = 0; chunk < nChunks; ++chunk) {
        const int colBase = chunk * 64;

        // stage next D chunk through registers (global reads overlap prior tail)
        float4 v[8];
        #pragma unroll
        for (int i = 0; i < 8; ++i) {
            int e  = tid + 256 * i;        // 2048 float4
            int r  = e >> 5;
            int kc = e & 31;
            v[i] = *(const float4*)(Dm + (size_t)(colBase + r) * DDIM + kc * 4);
        }
        __syncthreads();   // prior chunk's compute done reading Ds
        #pragma unroll
        for (int i = 0; i < 8; ++i) {
            int e  = tid + 256 * i;
            int r  = e >> 5;
            int kc = e & 31;
            *(float4*)(Ds + r * SQ_STRIDE + kc * 4) = v[i];
        }
        __syncthreads();

        unsigned long long acc[4][8];
        #pragma unroll
        for (int i = 0; i < 4; ++i)
            #pragma unroll
            for (int j = 0; j < 8; ++j) acc[i][j] = 0ull;

        #pragma unroll 8
        for (int kq = 0; kq < DDIM / 4; ++kq) {
            ulonglong2 a[4], b[8];
            #pragma unroll
            for (int i = 0; i < 4; ++i)
                a[i] = *(const ulonglong2*)(Qs + (ty + 32 * i) * SQ_STRIDE + kq * 4);
            #pragma unroll
            for (int j = 0; j < 8; ++j)
                b[j] = *(const ulonglong2*)(Ds + (tx + 8 * j) * SQ_STRIDE + kq * 4);
            #pragma unroll
            for (int i = 0; i < 4; ++i)
                #pragma unroll
                for (int j = 0; j < 8; ++j) {
                    ffma2(acc[i][j], a[i].x, b[j].x);
                    ffma2(acc[i][j], a[i].y, b[j].y);
                }
        }

        #pragma unroll
        for (int i = 0; i < 4; ++i)
            #pragma unroll
            for (int j = 0; j < 8; ++j) {
                float lo = __uint_as_float((unsigned)acc[i][j]);
                float hi = __uint_as_float((unsigned)(acc[i][j] >> 32));
                float s = lo + hi;
                int cj = colBase + tx + 8 * j;
                if (cj == ri[i]) s -= 1.0e6f;   // diagonal mask
                rmax[i] = fmaxf(rmax[i], s);
            }
    }

    // reduce rmax across tx (8 partials per row) via smem (reuse Ds region)
    __syncthreads();
    #pragma unroll
    for (int i = 0; i < 4; ++i)
        Ds[(ty + 32 * i) * 8 + tx] = rmax[i];
    __syncthreads();
    if (tid < 128) {
        float m = -3.0e38f;
        #pragma unroll
        for (int j = 0; j < 8; ++j) m = fmaxf(m, Ds[tid * 8 + j]);
        g_rowmax[rowBase + tid] = m;
    }
}

// ---------------------------------------------------------------------------
// Kernel C: deterministic final reduction (single block, fixed-order tree).
// ---------------------------------------------------------------------------
__global__ void finalize_kernel(float* __restrict__ out, int B) {
    __shared__ float sm[256];
    float s = 0.0f;
    for (int b = threadIdx.x; b < B; b += 256)
        s += g_term1[b] + softplusf(g_rowmax[b] - g_pos[b]);
    sm[threadIdx.x] = s;
    __syncthreads();
    #pragma unroll
    for (int off = 128; off > 0; off >>= 1) {
        if (threadIdx.x < off) sm[threadIdx.x] += sm[threadIdx.x + off];
        __syncthreads();
    }
    if (threadIdx.x == 0) out[0] = sm[0] / (2.0f * (float)B);
}

// ---------------------------------------------------------------------------
extern "C" void kernel_launch(void* const* d_in, const int* in_sizes, int n_in,
                              void* d_out, int out_size) {
    const float* q  = (const float*)d_in[0];
    const float* dd = (const float*)d_in[1];
    const float* nd = (const float*)d_in[2];
    float* out = (float*)d_out;

    int B = in_sizes[0] / DDIM;   // 16384

    size_t smem = (size_t)(128 * SQ_STRIDE + 64 * SQ_STRIDE) * sizeof(float); // 101376 B
    cudaFuncSetAttribute(inbatch_kernel,
                         cudaFuncAttributeMaxDynamicSharedMemorySize, (int)smem);

    pairwise_kernel<<<(B * 32) / 256, 256>>>(q, dd, nd, B);
    inbatch_kernel<<<B / 128, 256, smem>>>(q, dd, B);
    finalize_kernel<<<1, 256>>>(out, B);
}

// round 3
// speedup vs baseline: 4.1708x; 4.1708x over previous
#include <cuda_runtime.h>
#include <cuda_bf16.h>
#include <cstdint>

// ---------------------------------------------------------------------------
// Problem shape
// ---------------------------------------------------------------------------
#define BSZ    16384
#define DDIM   128
#define KP     256            // packed K: [hi(128) | lo(128)] bf16
#define TILE_N 128
#define NT     (BSZ / TILE_N) // 128 col tiles
#define BIGV   1.0e6f
#define PITCHB 528            // smem row pitch in bytes (512 data + 16 pad)

// Scratch (device globals; allocation-free rule)
__device__ __align__(128) __nv_bfloat16 g_Qp[BSZ * KP];   // 8 MB
__device__ __align__(128) __nv_bfloat16 g_Dp[BSZ * KP];   // 8 MB
__device__ float g_pos[BSZ];
__device__ float g_term1[BSZ];
__device__ float g_rowmax[BSZ];

// ---------------------------------------------------------------------------
// helpers
// ---------------------------------------------------------------------------
__device__ __forceinline__ uint32_t smem_to_u32(const void* p) {
    uint32_t a;
    asm("{ .reg .u64 t; cvta.to.shared.u64 t, %1; cvt.u32.u64 %0, t; }" : "=r"(a) : "l"(p));
    return a;
}
__device__ __forceinline__ void cpasync16(uint32_t s, const void* g) {
    asm volatile("cp.async.cg.shared.global [%0], [%1], 16;" :: "r"(s), "l"(g));
}
#define CP_COMMIT() asm volatile("cp.async.commit_group;" ::: "memory")
#define CP_WAIT(n)  asm volatile("cp.async.wait_group %0;" :: "n"(n) : "memory")

__device__ __forceinline__ void ldsm4(uint32_t* r, uint32_t addr) {
    asm volatile("ldmatrix.sync.aligned.m8n8.x4.shared.b16 {%0,%1,%2,%3}, [%4];"
                 : "=r"(r[0]), "=r"(r[1]), "=r"(r[2]), "=r"(r[3]) : "r"(addr));
}
__device__ __forceinline__ void mma16816(float* c, const uint32_t* a, uint32_t b0, uint32_t b1) {
    asm volatile("mma.sync.aligned.m16n8k16.row.col.f32.bf16.bf16.f32 "
                 "{%0,%1,%2,%3}, {%4,%5,%6,%7}, {%8,%9}, {%0,%1,%2,%3};"
                 : "+f"(c[0]), "+f"(c[1]), "+f"(c[2]), "+f"(c[3])
                 : "r"(a[0]), "r"(a[1]), "r"(a[2]), "r"(a[3]), "r"(b0), "r"(b1));
}
__device__ __forceinline__ float softplusf(float x) {
    return x > 20.0f ? x : log1pf(__expf(x));
}

// ---------------------------------------------------------------------------
// prep: fp32 -> bf16 hi|lo packed rows of 256
// ---------------------------------------------------------------------------
__global__ void prep_kernel(const float* __restrict__ src, __nv_bfloat16* __restrict__ dst) {
    int idx = blockIdx.x * blockDim.x + threadIdx.x;   // float4 index
    float4 v = ((const float4*)src)[idx];
    int row = idx >> 5;
    int k4  = (idx & 31) * 4;
    float x[4] = {v.x, v.y, v.z, v.w};
    __nv_bfloat16 h[4], l[4];
    #pragma unroll
    for (int i = 0; i < 4; ++i) {
        h[i] = __float2bfloat16(x[i]);
        l[i] = __float2bfloat16(x[i] - __bfloat162float(h[i]));
    }
    __nv_bfloat16* base = dst + (size_t)row * KP;
    *(__nv_bfloat162*)(base + k4)           = __nv_bfloat162(h[0], h[1]);
    *(__nv_bfloat162*)(base + k4 + 2)       = __nv_bfloat162(h[2], h[3]);
    *(__nv_bfloat162*)(base + 128 + k4)     = __nv_bfloat162(l[0], l[1]);
    *(__nv_bfloat162*)(base + 128 + k4 + 2) = __nv_bfloat162(l[2], l[3]);
}

// ---------------------------------------------------------------------------
// pairwise dots (fp32 exact)
// ---------------------------------------------------------------------------
__global__ void pairwise_kernel(const float* __restrict__ q, const float* __restrict__ d,
                                const float* __restrict__ nd, int B) {
    int warp = (blockIdx.x * blockDim.x + threadIdx.x) >> 5;
    int lane = threadIdx.x & 31;
    if (warp >= B) return;
    const float4 qv = *(const float4*)(q  + (size_t)warp * DDIM + lane * 4);
    const float4 dv = *(const float4*)(d  + (size_t)warp * DDIM + lane * 4);
    const float4 nv = *(const float4*)(nd + (size_t)warp * DDIM + lane * 4);
    float pos = qv.x * dv.x + qv.y * dv.y + qv.z * dv.z + qv.w * dv.w;
    float neg = qv.x * nv.x + qv.y * nv.y + qv.z * nv.z + qv.w * nv.w;
    #pragma unroll
    for (int off = 16; off > 0; off >>= 1) {
        pos += __shfl_xor_sync(0xFFFFFFFFu, pos, off);
        neg += __shfl_xor_sync(0xFFFFFFFFu, neg, off);
    }
    if (lane == 0) { g_pos[warp] = pos; g_term1[warp] = softplusf(neg - pos); }
}

// ---------------------------------------------------------------------------
// in-batch max-GEMM via mma.sync bf16 (HMMA). 128 CTAs x 256 threads.
// Warp grid 2(M) x 4(N): warp tile 64x32. A tile resident, B double-buffered.
// ---------------------------------------------------------------------------
#define SMEM_A  0
#define SMEM_B0 (128 * PITCHB)
#define SMEM_B1 (2 * 128 * PITCHB)
#define SMEM_TOTAL (3 * 128 * PITCHB)   // 202752 B

__device__ __forceinline__ void load_tile(uint32_t dst, const __nv_bfloat16* src,
                                          int rowBase, int tid) {
    const char* s = (const char*)(src + (size_t)rowBase * KP);
    #pragma unroll
    for (int i = 0; i < 16; ++i) {
        int e = tid + 256 * i;     // 16B chunk id, 4096 total
        int r = e >> 5;
        int c = e & 31;
        cpasync16(dst + r * PITCHB + c * 16, s + (size_t)r * 512 + c * 16);
    }
}

__global__ void __launch_bounds__(256, 1)
inbatch_kernel() {
    extern __shared__ __align__(1024) char smem[];
    const uint32_t sb = smem_to_u32(smem);
    const int tid  = threadIdx.x;
    const int wid  = tid >> 5;
    const int lane = tid & 31;
    const int wm   = wid >> 2;        // 0..1
    const int wn   = wid & 3;         // 0..3
    const int bid  = blockIdx.x;
    const int rowBase = bid * 128;

    // per-lane ldmatrix bases
    // A: row = wm*64 + mi*16 + (lane&15); colbyte = ks*32 + (lane&16)
    const uint32_t aBase = sb + SMEM_A + (uint32_t)((wm * 64 + (lane & 15)) * PITCHB + (lane & 16));
    // B: row = wn*32 + np*16 + ((lane>>4)<<3) + (lane&7); colbyte = ks*32 + ((lane&8)<<1)
    const uint32_t bRow  = (uint32_t)(wn * 32 + ((lane >> 4) << 3) + (lane & 7));
    const uint32_t bOffC = (uint32_t)((lane & 8) << 1);

    // prologue: A tile + B tile 0
    load_tile(sb + SMEM_A,  g_Qp, rowBase, tid);
    load_tile(sb + SMEM_B0, g_Dp, 0, tid);
    CP_COMMIT();

    float rmax[8];
    #pragma unroll
    for (int i = 0; i < 8; ++i) rmax[i] = -3.0e38f;

    for (int t = 0; t < NT; ++t) {
        CP_WAIT(0);
        __syncthreads();

        // prefetch next B tile into the other buffer
        if (t + 1 < NT) {
            uint32_t dst = sb + (((t + 1) & 1) ? SMEM_B1 : SMEM_B0);
            load_tile(dst, g_Dp, (t + 1) * TILE_N, tid);
            CP_COMMIT();
        }

        const uint32_t bBase = sb + ((t & 1) ? SMEM_B1 : SMEM_B0) + bRow * PITCHB + bOffC;

        float acc[4][4][4];
        #pragma unroll
        for (int mi = 0; mi < 4; ++mi)
            #pragma unroll
            for (int ni = 0; ni < 4; ++ni)
                #pragma unroll
                for (int r = 0; r < 4; ++r) acc[mi][ni][r] = 0.0f;

        #pragma unroll
        for (int ks = 0; ks < 16; ++ks) {
            uint32_t a[4][4];
            #pragma unroll
            for (int mi = 0; mi < 4; ++mi)
                ldsm4(a[mi], aBase + (uint32_t)(mi * 16 * PITCHB + ks * 32));
            uint32_t b[2][4];
            #pragma unroll
            for (int np = 0; np < 2; ++np)
                ldsm4(b[np], bBase + (uint32_t)(np * 16 * PITCHB + ks * 32));
            #pragma unroll
            for (int mi = 0; mi < 4; ++mi)
                #pragma unroll
                for (int ni = 0; ni < 4; ++ni)
                    mma16816(acc[mi][ni], a[mi], b[ni >> 1][(ni & 1) * 2], b[ni >> 1][(ni & 1) * 2 + 1]);
        }

        // fold tile into running row max
        if (t != bid) {
            #pragma unroll
            for (int mi = 0; mi < 4; ++mi)
                #pragma unroll
                for (int ni = 0; ni < 4; ++ni) {
                    rmax[mi * 2 + 0] = fmaxf(rmax[mi * 2 + 0], fmaxf(acc[mi][ni][0], acc[mi][ni][1]));
                    rmax[mi * 2 + 1] = fmaxf(rmax[mi * 2 + 1], fmaxf(acc[mi][ni][2], acc[mi][ni][3]));
                }
        } else {
            // diagonal tile: local row == local col gets -BIG
            #pragma unroll
            for (int mi = 0; mi < 4; ++mi) {
                int r0 = wm * 64 + mi * 16 + (lane >> 2);   // local rows r0, r0+8
                #pragma unroll
                for (int ni = 0; ni < 4; ++ni) {
                    int c0 = wn * 32 + ni * 8 + (lane & 3) * 2;
                    float v0 = acc[mi][ni][0]; if (c0     == r0)     v0 -= BIGV;
                    float v1 = acc[mi][ni][1]; if (c0 + 1 == r0)     v1 -= BIGV;
                    float v2 = acc[mi][ni][2]; if (c0     == r0 + 8) v2 -= BIGV;
                    float v3 = acc[mi][ni][3]; if (c0 + 1 == r0 + 8) v3 -= BIGV;
                    rmax[mi * 2 + 0] = fmaxf(rmax[mi * 2 + 0], fmaxf(v0, v1));
                    rmax[mi * 2 + 1] = fmaxf(rmax[mi * 2 + 1], fmaxf(v2, v3));
                }
            }
        }
    }

    // reduce across lane quads (cols within warp)
    #pragma unroll
    for (int i = 0; i < 8; ++i) {
        rmax[i] = fmaxf(rmax[i], __shfl_xor_sync(0xFFFFFFFFu, rmax[i], 1));
        rmax[i] = fmaxf(rmax[i], __shfl_xor_sync(0xFFFFFFFFu, rmax[i], 2));
    }
    // reduce across the 4 N-warps via smem scratch (reuse B0 region)
    __syncthreads();
    float* red = (float*)(smem + SMEM_B0);   // [128 rows][4]
    if ((lane & 3) == 0) {
        #pragma unroll
        for (int mi = 0; mi < 4; ++mi) {
            int rA = wm * 64 + mi * 16 + (lane >> 2);
            red[rA * 4 + wn]       = rmax[mi * 2 + 0];
            red[(rA + 8) * 4 + wn] = rmax[mi * 2 + 1];
        }
    }
    __syncthreads();
    if (tid < 128) {
        float m = fmaxf(fmaxf(red[tid * 4 + 0], red[tid * 4 + 1]),
                        fmaxf(red[tid * 4 + 2], red[tid * 4 + 3]));
        g_rowmax[rowBase + tid] = m;
    }
}

// ---------------------------------------------------------------------------
// final deterministic reduction
// ---------------------------------------------------------------------------
__global__ void finalize_kernel(float* __restrict__ out, int B) {
    __shared__ float sm[256];
    float s = 0.0f;
    for (int b = threadIdx.x; b < B; b += 256)
        s += g_term1[b] + softplusf(g_rowmax[b] - g_pos[b]);
    sm[threadIdx.x] = s;
    __syncthreads();
    #pragma unroll
    for (int off = 128; off > 0; off >>= 1) {
        if (threadIdx.x < off) sm[threadIdx.x] += sm[threadIdx.x + off];
        __syncthreads();
    }
    if (threadIdx.x == 0) out[0] = sm[0] / (2.0f * (float)B);
}

// ---------------------------------------------------------------------------
extern "C" void kernel_launch(void* const* d_in, const int* in_sizes, int n_in,
                              void* d_out, int out_size) {
    const float* q  = (const float*)d_in[0];
    const float* dd = (const float*)d_in[1];
    const float* nd = (const float*)d_in[2];
    float* out = (float*)d_out;
    int B = in_sizes[0] / DDIM;   // 16384

    __nv_bfloat16 *qp = nullptr, *dp = nullptr;
    cudaGetSymbolAddress((void**)&qp, g_Qp);
    cudaGetSymbolAddress((void**)&dp, g_Dp);

    cudaFuncSetAttribute(inbatch_kernel, cudaFuncAttributeMaxDynamicSharedMemorySize, SMEM_TOTAL);

    int prepBlocks = (B * DDIM / 4) / 256;   // 2048
    prep_kernel<<<prepBlocks, 256>>>(q, qp);
    prep_kernel<<<prepBlocks, 256>>>(dd, dp);
    pairwise_kernel<<<(B * 32) / 256, 256>>>(q, dd, nd, B);
    inbatch_kernel<<<B / 128, 256, SMEM_TOTAL>>>();
    finalize_kernel<<<1, 256>>>(out, B);
}

// round 4
// speedup vs baseline: 8.5406x; 2.0477x over previous
#include <cuda_runtime.h>
#include <cuda_bf16.h>
#include <cstdint>

// ---------------------------------------------------------------------------
// Problem shape / tiling
// ---------------------------------------------------------------------------
#define BSZ    16384
#define DDIM   128
#define TILE_N 128
#define BIGV   1.0e6f
#define PITCH  272               // smem row pitch bytes (256 data + 16 pad)
#define NRT    (BSZ / 128)       // 128 row tiles
#define NCHUNK 16                // col chunks per row tile (1024 cols each)
#define NITEMS (NRT * NCHUNK)    // 2048 work items
#define CHUNK_TILES 8            // 128-col B tiles per chunk
#define GRID_PERS 296            // 2 CTAs per SM x 148

// Scratch
__device__ __align__(128) __nv_bfloat16 g_Qb[BSZ * DDIM];   // 4 MB
__device__ __align__(128) __nv_bfloat16 g_Db[BSZ * DDIM];   // 4 MB
__device__ float    g_pos[BSZ];
__device__ float    g_term1[BSZ];
__device__ unsigned g_rowmax_enc[BSZ];
__device__ int      g_ctr;

// ---------------------------------------------------------------------------
// helpers
// ---------------------------------------------------------------------------
__device__ __forceinline__ uint32_t smem_to_u32(const void* p) {
    uint32_t a;
    asm("{ .reg .u64 t; cvta.to.shared.u64 t, %1; cvt.u32.u64 %0, t; }" : "=r"(a) : "l"(p));
    return a;
}
__device__ __forceinline__ void cpasync16(uint32_t s, const void* g) {
    asm volatile("cp.async.cg.shared.global [%0], [%1], 16;" :: "r"(s), "l"(g));
}
#define CP_COMMIT() asm volatile("cp.async.commit_group;" ::: "memory")
#define CP_WAIT0()  asm volatile("cp.async.wait_group 0;" ::: "memory")

__device__ __forceinline__ void ldsm4(uint32_t* r, uint32_t addr) {
    asm volatile("ldmatrix.sync.aligned.m8n8.x4.shared.b16 {%0,%1,%2,%3}, [%4];"
                 : "=r"(r[0]), "=r"(r[1]), "=r"(r[2]), "=r"(r[3]) : "r"(addr));
}
__device__ __forceinline__ void mma16816(float* c, const uint32_t* a, uint32_t b0, uint32_t b1) {
    asm volatile("mma.sync.aligned.m16n8k16.row.col.f32.bf16.bf16.f32 "
                 "{%0,%1,%2,%3}, {%4,%5,%6,%7}, {%8,%9}, {%0,%1,%2,%3};"
                 : "+f"(c[0]), "+f"(c[1]), "+f"(c[2]), "+f"(c[3])
                 : "r"(a[0]), "r"(a[1]), "r"(a[2]), "r"(a[3]), "r"(b0), "r"(b1));
}
__device__ __forceinline__ float softplusf(float x) {
    return x > 20.0f ? x : log1pf(__expf(x));
}
// order-preserving float<->uint for atomicMax
__device__ __forceinline__ unsigned enc_f(float x) {
    unsigned u = __float_as_uint(x);
    return (u & 0x80000000u) ? ~u : (u | 0x80000000u);
}
__device__ __forceinline__ float dec_f(unsigned e) {
    unsigned u = (e & 0x80000000u) ? (e & 0x7FFFFFFFu) : ~e;
    return __uint_as_float(u);
}

// ---------------------------------------------------------------------------
// init: reset work counter + row maxima (every launch/replay)
// ---------------------------------------------------------------------------
__global__ void init_kernel() {
    int i = blockIdx.x * blockDim.x + threadIdx.x;
    if (i < BSZ) g_rowmax_enc[i] = 0u;      // below every real encoding
    if (i == 0) g_ctr = 0;
}

// ---------------------------------------------------------------------------
// prep: fp32 -> bf16 (hi only)
// ---------------------------------------------------------------------------
__global__ void prep_kernel(const float* __restrict__ src, __nv_bfloat16* __restrict__ dst) {
    int idx = blockIdx.x * blockDim.x + threadIdx.x;   // float4 index
    float4 v = ((const float4*)src)[idx];
    __nv_bfloat162 p0 = __nv_bfloat162(__float2bfloat16(v.x), __float2bfloat16(v.y));
    __nv_bfloat162 p1 = __nv_bfloat162(__float2bfloat16(v.z), __float2bfloat16(v.w));
    *(__nv_bfloat162*)(dst + idx * 4)     = p0;
    *(__nv_bfloat162*)(dst + idx * 4 + 2) = p1;
}

// ---------------------------------------------------------------------------
// pairwise dots (fp32 exact)
// ---------------------------------------------------------------------------
__global__ void pairwise_kernel(const float* __restrict__ q, const float* __restrict__ d,
                                const float* __restrict__ nd, int B) {
    int warp = (blockIdx.x * blockDim.x + threadIdx.x) >> 5;
    int lane = threadIdx.x & 31;
    if (warp >= B) return;
    const float4 qv = *(const float4*)(q  + (size_t)warp * DDIM + lane * 4);
    const float4 dv = *(const float4*)(d  + (size_t)warp * DDIM + lane * 4);
    const float4 nv = *(const float4*)(nd + (size_t)warp * DDIM + lane * 4);
    float pos = qv.x * dv.x + qv.y * dv.y + qv.z * dv.z + qv.w * dv.w;
    float neg = qv.x * nv.x + qv.y * nv.y + qv.z * nv.z + qv.w * nv.w;
    #pragma unroll
    for (int off = 16; off > 0; off >>= 1) {
        pos += __shfl_xor_sync(0xFFFFFFFFu, pos, off);
        neg += __shfl_xor_sync(0xFFFFFFFFu, neg, off);
    }
    if (lane == 0) { g_pos[warp] = pos; g_term1[warp] = softplusf(neg - pos); }
}

// ---------------------------------------------------------------------------
// persistent max-GEMM: 296 CTAs pop (row-tile, col-chunk) items dynamically.
// CTA tile 128x128, 8 warps (2x4), warp tile 64x32, K=128 bf16.
// ---------------------------------------------------------------------------
#define SMEM_A    0
#define SMEM_B0   (128 * PITCH)
#define SMEM_B1   (2 * 128 * PITCH)
#define SMEM_RED  (3 * 128 * PITCH)
#define SMEM_TOTAL (3 * 128 * PITCH + 2048)   // 104448 + 2048 = 106496 B

__device__ __forceinline__ void load_tile128(uint32_t dst, const __nv_bfloat16* src,
                                             int rowBase, int tid) {
    const char* s = (const char*)(src + (size_t)rowBase * DDIM);
    #pragma unroll
    for (int i = 0; i < 8; ++i) {
        int e = tid + 256 * i;     // 16B chunk id, 2048 total (128 rows x 16)
        int r = e >> 4;
        int c = e & 15;
        cpasync16(dst + r * PITCH + c * 16, s + (size_t)r * 256 + c * 16);
    }
}

__global__ void __launch_bounds__(256, 2)
inbatch_kernel() {
    extern __shared__ __align__(1024) char smem[];
    __shared__ int s_item;
    const uint32_t sb = smem_to_u32(smem);
    const int tid  = threadIdx.x;
    const int lane = tid & 31;
    const int wid  = tid >> 5;
    const int wm   = wid >> 2;        // 0..1
    const int wn   = wid & 3;         // 0..3

    const uint32_t aBase = sb + SMEM_A + (uint32_t)((wm * 64 + (lane & 15)) * PITCH + (lane & 16));
    const uint32_t bRow  = (uint32_t)(wn * 32 + ((lane >> 4) << 3) + (lane & 7));
    const uint32_t bOffC = (uint32_t)((lane & 8) << 1);

    float* red = (float*)(smem + SMEM_RED);   // [128][4]

    while (true) {
        if (tid == 0) s_item = atomicAdd(&g_ctr, 1);
        __syncthreads();
        const int item = s_item;
        if (item >= NITEMS) break;

        const int rt = item >> 4;            // row tile 0..127
        const int cc = item & 15;            // col chunk 0..15
        const int rowBase  = rt * 128;
        const int tileBase = cc * CHUNK_TILES;   // global 128-col tile index base

        // prologue: A + first B tile as one cp.async group
        load_tile128(sb + SMEM_A,  g_Qb, rowBase, tid);
        load_tile128(sb + SMEM_B0, g_Db, tileBase * TILE_N, tid);
        CP_COMMIT();

        float rmax[8];
        #pragma unroll
        for (int i = 0; i < 8; ++i) rmax[i] = -3.0e38f;

        for (int j = 0; j < CHUNK_TILES; ++j) {
            CP_WAIT0();
            __syncthreads();
            if (j + 1 < CHUNK_TILES) {
                uint32_t dst = sb + (((j + 1) & 1) ? SMEM_B1 : SMEM_B0);
                load_tile128(dst, g_Db, (tileBase + j + 1) * TILE_N, tid);
                CP_COMMIT();
            }
            const uint32_t bBase = sb + ((j & 1) ? SMEM_B1 : SMEM_B0) + bRow * PITCH + bOffC;

            float acc[4][4][4];
            #pragma unroll
            for (int mi = 0; mi < 4; ++mi)
                #pragma unroll
                for (int ni = 0; ni < 4; ++ni)
                    #pragma unroll
                    for (int r = 0; r < 4; ++r) acc[mi][ni][r] = 0.0f;

            #pragma unroll
            for (int ks = 0; ks < 8; ++ks) {
                uint32_t a[4][4];
                #pragma unroll
                for (int mi = 0; mi < 4; ++mi)
                    ldsm4(a[mi], aBase + (uint32_t)(mi * 16 * PITCH + ks * 32));
                uint32_t b[2][4];
                #pragma unroll
                for (int np = 0; np < 2; ++np)
                    ldsm4(b[np], bBase + (uint32_t)(np * 16 * PITCH + ks * 32));
                #pragma unroll
                for (int mi = 0; mi < 4; ++mi)
                    #pragma unroll
                    for (int ni = 0; ni < 4; ++ni)
                        mma16816(acc[mi][ni], a[mi],
                                 b[ni >> 1][(ni & 1) * 2], b[ni >> 1][(ni & 1) * 2 + 1]);
            }

            if (tileBase + j != rt) {
                #pragma unroll
                for (int mi = 0; mi < 4; ++mi)
                    #pragma unroll
                    for (int ni = 0; ni < 4; ++ni) {
                        rmax[mi * 2 + 0] = fmaxf(rmax[mi * 2 + 0], fmaxf(acc[mi][ni][0], acc[mi][ni][1]));
                        rmax[mi * 2 + 1] = fmaxf(rmax[mi * 2 + 1], fmaxf(acc[mi][ni][2], acc[mi][ni][3]));
                    }
            } else {
                #pragma unroll
                for (int mi = 0; mi < 4; ++mi) {
                    int r0 = wm * 64 + mi * 16 + (lane >> 2);
                    #pragma unroll
                    for (int ni = 0; ni < 4; ++ni) {
                        int c0 = wn * 32 + ni * 8 + (lane & 3) * 2;
                        float v0 = acc[mi][ni][0]; if (c0     == r0)     v0 -= BIGV;
                        float v1 = acc[mi][ni][1]; if (c0 + 1 == r0)     v1 -= BIGV;
                        float v2 = acc[mi][ni][2]; if (c0     == r0 + 8) v2 -= BIGV;
                        float v3 = acc[mi][ni][3]; if (c0 + 1 == r0 + 8) v3 -= BIGV;
                        rmax[mi * 2 + 0] = fmaxf(rmax[mi * 2 + 0], fmaxf(v0, v1));
                        rmax[mi * 2 + 1] = fmaxf(rmax[mi * 2 + 1], fmaxf(v2, v3));
                    }
                }
            }
        }

        // reduce lane quads (cols within warp)
        #pragma unroll
        for (int i = 0; i < 8; ++i) {
            rmax[i] = fmaxf(rmax[i], __shfl_xor_sync(0xFFFFFFFFu, rmax[i], 1));
            rmax[i] = fmaxf(rmax[i], __shfl_xor_sync(0xFFFFFFFFu, rmax[i], 2));
        }
        __syncthreads();
        if ((lane & 3) == 0) {
            #pragma unroll
            for (int mi = 0; mi < 4; ++mi) {
                int rA = wm * 64 + mi * 16 + (lane >> 2);
                red[rA * 4 + wn]       = rmax[mi * 2 + 0];
                red[(rA + 8) * 4 + wn] = rmax[mi * 2 + 1];
            }
        }
        __syncthreads();
        if (tid < 128) {
            float m = fmaxf(fmaxf(red[tid * 4 + 0], red[tid * 4 + 1]),
                            fmaxf(red[tid * 4 + 2], red[tid * 4 + 3]));
            atomicMax(&g_rowmax_enc[rowBase + tid], enc_f(m));
        }
        __syncthreads();
    }
}

// ---------------------------------------------------------------------------
// final deterministic reduction
// ---------------------------------------------------------------------------
__global__ void finalize_kernel(float* __restrict__ out, int B) {
    __shared__ float sm[256];
    float s = 0.0f;
    for (int b = threadIdx.x; b < B; b += 256)
        s += g_term1[b] + softplusf(dec_f(g_rowmax_enc[b]) - g_pos[b]);
    sm[threadIdx.x] = s;
    __syncthreads();
    #pragma unroll
    for (int off = 128; off > 0; off >>= 1) {
        if (threadIdx.x < off) sm[threadIdx.x] += sm[threadIdx.x + off];
        __syncthreads();
    }
    if (threadIdx.x == 0) out[0] = sm[0] / (2.0f * (float)B);
}

// ---------------------------------------------------------------------------
extern "C" void kernel_launch(void* const* d_in, const int* in_sizes, int n_in,
                              void* d_out, int out_size) {
    const float* q  = (const float*)d_in[0];
    const float* dd = (const float*)d_in[1];
    const float* nd = (const float*)d_in[2];
    float* out = (float*)d_out;
    int B = in_sizes[0] / DDIM;   // 16384

    __nv_bfloat16 *qb = nullptr, *db = nullptr;
    cudaGetSymbolAddress((void**)&qb, g_Qb);
    cudaGetSymbolAddress((void**)&db, g_Db);

    cudaFuncSetAttribute(inbatch_kernel, cudaFuncAttributeMaxDynamicSharedMemorySize, SMEM_TOTAL);

    init_kernel<<<(B + 255) / 256, 256>>>();
    int prepBlocks = (B * DDIM / 4) / 256;   // 2048
    prep_kernel<<<prepBlocks, 256>>>(q, qb);
    prep_kernel<<<prepBlocks, 256>>>(dd, db);
    pairwise_kernel<<<(B * 32) / 256, 256>>>(q, dd, nd, B);
    inbatch_kernel<<<GRID_PERS, 256, SMEM_TOTAL>>>();
    finalize_kernel<<<1, 256>>>(out, B);
}

// round 5
// speedup vs baseline: 9.3570x; 1.0956x over previous
#include <cuda_runtime.h>
#include <cuda_fp16.h>
#include <cstdint>

// ---------------------------------------------------------------------------
// Problem shape / tiling
// ---------------------------------------------------------------------------
#define BSZ    16384
#define DDIM   128
#define TILE_N 128
#define PITCH  272               // smem row pitch bytes (256 data + 16 pad)
#define NRT    (BSZ / 128)       // 128 row tiles
#define NCHUNK 16                // col chunks per row tile (1024 cols)
#define NITEMS (NRT * NCHUNK)    // 2048 work items
#define CHUNK_TILES 8
#define GRID_PERS 296            // 2 CTAs/SM x 148
#define NEGINF_LO 0x0000FC00u
#define NEGINF_HI 0xFC000000u

// Scratch
__device__ __align__(128) __half g_Qh[BSZ * DDIM];   // 4 MB
__device__ __align__(128) __half g_Dh[BSZ * DDIM];   // 4 MB
__device__ float    g_pos[BSZ];
__device__ float    g_term1[BSZ];
__device__ unsigned g_rowmax_enc[BSZ];
__device__ float    g_part[64];
__device__ int      g_ctr;

// ---------------------------------------------------------------------------
// helpers
// ---------------------------------------------------------------------------
__device__ __forceinline__ uint32_t smem_to_u32(const void* p) {
    uint32_t a;
    asm("{ .reg .u64 t; cvta.to.shared.u64 t, %1; cvt.u32.u64 %0, t; }" : "=r"(a) : "l"(p));
    return a;
}
__device__ __forceinline__ void cpasync16(uint32_t s, const void* g) {
    asm volatile("cp.async.cg.shared.global [%0], [%1], 16;" :: "r"(s), "l"(g));
}
#define CP_COMMIT() asm volatile("cp.async.commit_group;" ::: "memory")
#define CP_WAIT0()  asm volatile("cp.async.wait_group 0;" ::: "memory")

__device__ __forceinline__ void ldsm4(uint32_t* r, uint32_t addr) {
    asm volatile("ldmatrix.sync.aligned.m8n8.x4.shared.b16 {%0,%1,%2,%3}, [%4];"
                 : "=r"(r[0]), "=r"(r[1]), "=r"(r[2]), "=r"(r[3]) : "r"(addr));
}
// f16 x f16 -> f16-accumulate HMMA
__device__ __forceinline__ void mma16816h(uint32_t* c, const uint32_t* a, uint32_t b0, uint32_t b1) {
    asm volatile("mma.sync.aligned.m16n8k16.row.col.f16.f16.f16.f16 "
                 "{%0,%1}, {%2,%3,%4,%5}, {%6,%7}, {%0,%1};"
                 : "+r"(c[0]), "+r"(c[1])
                 : "r"(a[0]), "r"(a[1]), "r"(a[2]), "r"(a[3]), "r"(b0), "r"(b1));
}
__device__ __forceinline__ uint32_t hmax2(uint32_t a, uint32_t b) {
    uint32_t d;
    asm("max.f16x2 %0, %1, %2;" : "=r"(d) : "r"(a), "r"(b));
    return d;
}
__device__ __forceinline__ float softplusf(float x) {
    return x > 20.0f ? x : log1pf(__expf(x));
}
__device__ __forceinline__ unsigned enc_f(float x) {
    unsigned u = __float_as_uint(x);
    return (u & 0x80000000u) ? ~u : (u | 0x80000000u);
}
__device__ __forceinline__ float dec_f(unsigned e) {
    unsigned u = (e & 0x80000000u) ? (e & 0x7FFFFFFFu) : ~e;
    return __uint_as_float(u);
}

// ---------------------------------------------------------------------------
// fused pre-pass: f32->f16 for Q and D, pairwise dots, init rowmax + counter.
// One warp per row.
// ---------------------------------------------------------------------------
__global__ void prep_fused(const float* __restrict__ q, const float* __restrict__ d,
                           const float* __restrict__ nd,
                           __half* __restrict__ qh, __half* __restrict__ dh) {
    int warp = (blockIdx.x * blockDim.x + threadIdx.x) >> 5;
    int lane = threadIdx.x & 31;
    if (warp >= BSZ) return;

    const float4 qv = *(const float4*)(q  + (size_t)warp * DDIM + lane * 4);
    const float4 dv = *(const float4*)(d  + (size_t)warp * DDIM + lane * 4);
    const float4 nv = *(const float4*)(nd + (size_t)warp * DDIM + lane * 4);

    // f16 conversions (vector stores, 8B per lane per matrix)
    __half2* qdst = (__half2*)(qh + (size_t)warp * DDIM + lane * 4);
    qdst[0] = __floats2half2_rn(qv.x, qv.y);
    qdst[1] = __floats2half2_rn(qv.z, qv.w);
    __half2* ddst = (__half2*)(dh + (size_t)warp * DDIM + lane * 4);
    ddst[0] = __floats2half2_rn(dv.x, dv.y);
    ddst[1] = __floats2half2_rn(dv.z, dv.w);

    float pos = qv.x * dv.x + qv.y * dv.y + qv.z * dv.z + qv.w * dv.w;
    float neg = qv.x * nv.x + qv.y * nv.y + qv.z * nv.z + qv.w * nv.w;
    #pragma unroll
    for (int off = 16; off > 0; off >>= 1) {
        pos += __shfl_xor_sync(0xFFFFFFFFu, pos, off);
        neg += __shfl_xor_sync(0xFFFFFFFFu, neg, off);
    }
    if (lane == 0) {
        g_pos[warp] = pos;
        g_term1[warp] = softplusf(neg - pos);
        g_rowmax_enc[warp] = 0u;
        if (warp == 0) g_ctr = 0;
    }
}

// ---------------------------------------------------------------------------
// persistent max-GEMM: f16 HMMA with f16 accumulators.
// ---------------------------------------------------------------------------
#define SMEM_A    0
#define SMEM_B0   (128 * PITCH)
#define SMEM_B1   (2 * 128 * PITCH)
#define SMEM_RED  (3 * 128 * PITCH)
#define SMEM_TOTAL (3 * 128 * PITCH + 2048)   // 106496 B

__device__ __forceinline__ void load_tile128(uint32_t dst, const __half* src,
                                             int rowBase, int tid) {
    const char* s = (const char*)(src + (size_t)rowBase * DDIM);
    #pragma unroll
    for (int i = 0; i < 8; ++i) {
        int e = tid + 256 * i;     // 16B chunk id, 2048 total (128 rows x 16)
        int r = e >> 4;
        int c = e & 15;
        cpasync16(dst + r * PITCH + c * 16, s + (size_t)r * 256 + c * 16);
    }
}

__global__ void __launch_bounds__(256, 2)
inbatch_kernel() {
    extern __shared__ __align__(1024) char smem[];
    __shared__ int s_item;
    const uint32_t sb = smem_to_u32(smem);
    const int tid  = threadIdx.x;
    const int lane = tid & 31;
    const int wid  = tid >> 5;
    const int wm   = wid >> 2;        // 0..1
    const int wn   = wid & 3;         // 0..3

    const uint32_t aBase = sb + SMEM_A + (uint32_t)((wm * 64 + (lane & 15)) * PITCH + (lane & 16));
    const uint32_t bRow  = (uint32_t)(wn * 32 + ((lane >> 4) << 3) + (lane & 7));
    const uint32_t bOffC = (uint32_t)((lane & 8) << 1);

    float* red = (float*)(smem + SMEM_RED);   // [128][4]

    while (true) {
        if (tid == 0) s_item = atomicAdd(&g_ctr, 1);
        __syncthreads();
        const int item = s_item;
        if (item >= NITEMS) break;

        const int rt = item >> 4;
        const int cc = item & 15;
        const int rowBase  = rt * 128;
        const int tileBase = cc * CHUNK_TILES;

        load_tile128(sb + SMEM_A,  g_Qh, rowBase, tid);
        load_tile128(sb + SMEM_B0, g_Dh, tileBase * TILE_N, tid);
        CP_COMMIT();

        // running row-max as packed f16x2: [mi][rr]; init -inf in both halves
        uint32_t rmax2[4][2];
        #pragma unroll
        for (int mi = 0; mi < 4; ++mi) { rmax2[mi][0] = 0xFC00FC00u; rmax2[mi][1] = 0xFC00FC00u; }

        for (int j = 0; j < CHUNK_TILES; ++j) {
            CP_WAIT0();
            __syncthreads();
            if (j + 1 < CHUNK_TILES) {
                uint32_t dst = sb + (((j + 1) & 1) ? SMEM_B1 : SMEM_B0);
                load_tile128(dst, g_Dh, (tileBase + j + 1) * TILE_N, tid);
                CP_COMMIT();
            }
            const uint32_t bBase = sb + ((j & 1) ? SMEM_B1 : SMEM_B0) + bRow * PITCH + bOffC;

            uint32_t acc[4][4][2];
            #pragma unroll
            for (int mi = 0; mi < 4; ++mi)
                #pragma unroll
                for (int ni = 0; ni < 4; ++ni) { acc[mi][ni][0] = 0u; acc[mi][ni][1] = 0u; }

            #pragma unroll
            for (int ks = 0; ks < 8; ++ks) {
                uint32_t a[4][4];
                #pragma unroll
                for (int mi = 0; mi < 4; ++mi)
                    ldsm4(a[mi], aBase + (uint32_t)(mi * 16 * PITCH + ks * 32));
                uint32_t b[2][4];
                #pragma unroll
                for (int np = 0; np < 2; ++np)
                    ldsm4(b[np], bBase + (uint32_t)(np * 16 * PITCH + ks * 32));
                #pragma unroll
                for (int mi = 0; mi < 4; ++mi)
                    #pragma unroll
                    for (int ni = 0; ni < 4; ++ni)
                        mma16816h(acc[mi][ni], a[mi],
                                  b[ni >> 1][(ni & 1) * 2], b[ni >> 1][(ni & 1) * 2 + 1]);
            }

            if (tileBase + j == rt) {
                // diagonal tile: splat -inf into diag elements (excludes them from max)
                #pragma unroll
                for (int mi = 0; mi < 4; ++mi) {
                    int r0 = wm * 64 + mi * 16 + (lane >> 2);
                    #pragma unroll
                    for (int ni = 0; ni < 4; ++ni) {
                        int c0 = wn * 32 + ni * 8 + (lane & 3) * 2;
                        if (c0     == r0)     acc[mi][ni][0] = (acc[mi][ni][0] & 0xFFFF0000u) | NEGINF_LO;
                        if (c0 + 1 == r0)     acc[mi][ni][0] = (acc[mi][ni][0] & 0x0000FFFFu) | NEGINF_HI;
                        if (c0     == r0 + 8) acc[mi][ni][1] = (acc[mi][ni][1] & 0xFFFF0000u) | NEGINF_LO;
                        if (c0 + 1 == r0 + 8) acc[mi][ni][1] = (acc[mi][ni][1] & 0x0000FFFFu) | NEGINF_HI;
                    }
                }
            }
            #pragma unroll
            for (int mi = 0; mi < 4; ++mi)
                #pragma unroll
                for (int ni = 0; ni < 4; ++ni) {
                    rmax2[mi][0] = hmax2(rmax2[mi][0], acc[mi][ni][0]);
                    rmax2[mi][1] = hmax2(rmax2[mi][1], acc[mi][ni][1]);
                }
        }

        // collapse f16x2 -> float per (mi, rr)
        float rmax[8];
        #pragma unroll
        for (int mi = 0; mi < 4; ++mi)
            #pragma unroll
            for (int rr = 0; rr < 2; ++rr) {
                __half2 h = *(__half2*)&rmax2[mi][rr];
                rmax[mi * 2 + rr] = fmaxf(__low2float(h), __high2float(h));
            }
        // reduce across lane quads (columns within warp)
        #pragma unroll
        for (int i = 0; i < 8; ++i) {
            rmax[i] = fmaxf(rmax[i], __shfl_xor_sync(0xFFFFFFFFu, rmax[i], 1));
            rmax[i] = fmaxf(rmax[i], __shfl_xor_sync(0xFFFFFFFFu, rmax[i], 2));
        }
        __syncthreads();
        if ((lane & 3) == 0) {
            #pragma unroll
            for (int mi = 0; mi < 4; ++mi) {
                int rA = wm * 64 + mi * 16 + (lane >> 2);
                red[rA * 4 + wn]       = rmax[mi * 2 + 0];
                red[(rA + 8) * 4 + wn] = rmax[mi * 2 + 1];
            }
        }
        __syncthreads();
        if (tid < 128) {
            float m = fmaxf(fmaxf(red[tid * 4 + 0], red[tid * 4 + 1]),
                            fmaxf(red[tid * 4 + 2], red[tid * 4 + 3]));
            atomicMax(&g_rowmax_enc[rowBase + tid], enc_f(m));
        }
        __syncthreads();
    }
}

// ---------------------------------------------------------------------------
// finalize: 64-block deterministic partials + tiny combiner
// ---------------------------------------------------------------------------
__global__ void finalize1_kernel() {
    __shared__ float sm[256];
    int base = blockIdx.x * 256;
    int b = base + threadIdx.x;
    float s = g_term1[b] + softplusf(dec_f(g_rowmax_enc[b]) - g_pos[b]);
    sm[threadIdx.x] = s;
    __syncthreads();
    #pragma unroll
    for (int off = 128; off > 0; off >>= 1) {
        if (threadIdx.x < off) sm[threadIdx.x] += sm[threadIdx.x + off];
        __syncthreads();
    }
    if (threadIdx.x == 0) g_part[blockIdx.x] = sm[0];
}
__global__ void finalize2_kernel(float* __restrict__ out, int B) {
    __shared__ float sm[64];
    sm[threadIdx.x] = g_part[threadIdx.x];
    __syncthreads();
    #pragma unroll
    for (int off = 32; off > 0; off >>= 1) {
        if (threadIdx.x < off) sm[threadIdx.x] += sm[threadIdx.x + off];
        __syncthreads();
    }
    if (threadIdx.x == 0) out[0] = sm[0] / (2.0f * (float)B);
}

// ---------------------------------------------------------------------------
extern "C" void kernel_launch(void* const* d_in, const int* in_sizes, int n_in,
                              void* d_out, int out_size) {
    const float* q  = (const float*)d_in[0];
    const float* dd = (const float*)d_in[1];
    const float* nd = (const float*)d_in[2];
    float* out = (float*)d_out;
    int B = in_sizes[0] / DDIM;   // 16384

    __half *qh = nullptr, *dh = nullptr;
    cudaGetSymbolAddress((void**)&qh, g_Qh);
    cudaGetSymbolAddress((void**)&dh, g_Dh);

    cudaFuncSetAttribute(inbatch_kernel, cudaFuncAttributeMaxDynamicSharedMemorySize, SMEM_TOTAL);

    prep_fused<<<(B * 32) / 256, 256>>>(q, dd, nd, qh, dh);
    inbatch_kernel<<<GRID_PERS, 256, SMEM_TOTAL>>>();
    finalize1_kernel<<<B / 256, 256>>>();   // 64 blocks
    finalize2_kernel<<<1, 64>>>(out, B);
}

// round 6
// speedup vs baseline: 9.6837x; 1.0349x over previous
#include <cuda_runtime.h>
#include <cuda_fp16.h>
#include <cstdint>

// ---------------------------------------------------------------------------
// Problem shape / tiling
// ---------------------------------------------------------------------------
#define BSZ    16384
#define DDIM   128
#define TILE_M 256               // rows per item
#define TILE_N 128               // cols per tile step
#define PITCH  272               // smem row pitch bytes (256 data + 16 pad)
#define NRT    (BSZ / TILE_M)    // 64 row tiles
#define NCHUNK 16                // col chunks per row tile (1024 cols)
#define NITEMS (NRT * NCHUNK)    // 1024 work items
#define CHUNK_TILES 8
#define GRID_PERS 148
#define NEGINF_LO 0x0000FC00u
#define NEGINF_HI 0xFC000000u

// Scratch
__device__ __align__(128) __half g_Qh[BSZ * DDIM];   // 4 MB
__device__ __align__(128) __half g_Dh[BSZ * DDIM];   // 4 MB
__device__ float    g_pos[BSZ];
__device__ float    g_term1[BSZ];
__device__ unsigned g_rowmax_enc[BSZ];
__device__ float    g_part[64];
__device__ int      g_ctr;

// ---------------------------------------------------------------------------
// helpers
// ---------------------------------------------------------------------------
__device__ __forceinline__ uint32_t smem_to_u32(const void* p) {
    uint32_t a;
    asm("{ .reg .u64 t; cvta.to.shared.u64 t, %1; cvt.u32.u64 %0, t; }" : "=r"(a) : "l"(p));
    return a;
}
__device__ __forceinline__ void cpasync16(uint32_t s, const void* g) {
    asm volatile("cp.async.cg.shared.global [%0], [%1], 16;" :: "r"(s), "l"(g));
}
#define CP_COMMIT() asm volatile("cp.async.commit_group;" ::: "memory")
#define CP_WAIT0()  asm volatile("cp.async.wait_group 0;" ::: "memory")

__device__ __forceinline__ void ldsm4(uint32_t* r, uint32_t addr) {
    asm volatile("ldmatrix.sync.aligned.m8n8.x4.shared.b16 {%0,%1,%2,%3}, [%4];"
                 : "=r"(r[0]), "=r"(r[1]), "=r"(r[2]), "=r"(r[3]) : "r"(addr));
}
__device__ __forceinline__ void mma16816h(uint32_t* c, const uint32_t* a, uint32_t b0, uint32_t b1) {
    asm volatile("mma.sync.aligned.m16n8k16.row.col.f16.f16.f16.f16 "
                 "{%0,%1}, {%2,%3,%4,%5}, {%6,%7}, {%0,%1};"
                 : "+r"(c[0]), "+r"(c[1])
                 : "r"(a[0]), "r"(a[1]), "r"(a[2]), "r"(a[3]), "r"(b0), "r"(b1));
}
__device__ __forceinline__ uint32_t hmax2(uint32_t a, uint32_t b) {
    uint32_t d;
    asm("max.f16x2 %0, %1, %2;" : "=r"(d) : "r"(a), "r"(b));
    return d;
}
__device__ __forceinline__ float softplusf(float x) {
    return x > 20.0f ? x : log1pf(__expf(x));
}
__device__ __forceinline__ unsigned enc_f(float x) {
    unsigned u = __float_as_uint(x);
    return (u & 0x80000000u) ? ~u : (u | 0x80000000u);
}
__device__ __forceinline__ float dec_f(unsigned e) {
    unsigned u = (e & 0x80000000u) ? (e & 0x7FFFFFFFu) : ~e;
    return __uint_as_float(u);
}

// ---------------------------------------------------------------------------
// fused pre-pass: f32->f16 (Q, D), pairwise dots, init rowmax + counter
// ---------------------------------------------------------------------------
__global__ void prep_fused(const float* __restrict__ q, const float* __restrict__ d,
                           const float* __restrict__ nd,
                           __half* __restrict__ qh, __half* __restrict__ dh) {
    int warp = (blockIdx.x * blockDim.x + threadIdx.x) >> 5;
    int lane = threadIdx.x & 31;
    if (warp >= BSZ) return;

    const float4 qv = *(const float4*)(q  + (size_t)warp * DDIM + lane * 4);
    const float4 dv = *(const float4*)(d  + (size_t)warp * DDIM + lane * 4);
    const float4 nv = *(const float4*)(nd + (size_t)warp * DDIM + lane * 4);

    __half2* qdst = (__half2*)(qh + (size_t)warp * DDIM + lane * 4);
    qdst[0] = __floats2half2_rn(qv.x, qv.y);
    qdst[1] = __floats2half2_rn(qv.z, qv.w);
    __half2* ddst = (__half2*)(dh + (size_t)warp * DDIM + lane * 4);
    ddst[0] = __floats2half2_rn(dv.x, dv.y);
    ddst[1] = __floats2half2_rn(dv.z, dv.w);

    float pos = qv.x * dv.x + qv.y * dv.y + qv.z * dv.z + qv.w * dv.w;
    float neg = qv.x * nv.x + qv.y * nv.y + qv.z * nv.z + qv.w * nv.w;
    #pragma unroll
    for (int off = 16; off > 0; off >>= 1) {
        pos += __shfl_xor_sync(0xFFFFFFFFu, pos, off);
        neg += __shfl_xor_sync(0xFFFFFFFFu, neg, off);
    }
    if (lane == 0) {
        g_pos[warp] = pos;
        g_term1[warp] = softplusf(neg - pos);
        g_rowmax_enc[warp] = 0u;
        if (warp == 0) g_ctr = 0;
    }
}

// ---------------------------------------------------------------------------
// persistent max-GEMM: 148 CTAs x 512 threads, item = 256 rows x 1024 cols.
// A double-buffered across items, B double-buffered across tiles,
// next item popped at tile 6 and prefetched during tile 7.
// ---------------------------------------------------------------------------
#define SMEM_A0   0
#define SMEM_A1   (TILE_M * PITCH)                 // 69632
#define SMEM_B0   (2 * TILE_M * PITCH)             // 139264
#define SMEM_B1   (2 * TILE_M * PITCH + 128 * PITCH)  // 174080
#define SMEM_RED  (2 * TILE_M * PITCH + 2 * 128 * PITCH)  // 208896
#define SMEM_TOTAL (SMEM_RED + TILE_M * 16)        // 212992 B

__device__ __forceinline__ void load_tileA(uint32_t dst, const __half* src,
                                           int rowBase, int tid) {
    const char* s = (const char*)(src + (size_t)rowBase * DDIM);
    #pragma unroll
    for (int i = 0; i < 8; ++i) {
        int e = tid + 512 * i;     // 4096 chunks (256 rows x 16)
        int r = e >> 4;
        int c = e & 15;
        cpasync16(dst + r * PITCH + c * 16, s + (size_t)r * 256 + c * 16);
    }
}
__device__ __forceinline__ void load_tileB(uint32_t dst, const __half* src,
                                           int rowBase, int tid) {
    const char* s = (const char*)(src + (size_t)rowBase * DDIM);
    #pragma unroll
    for (int i = 0; i < 4; ++i) {
        int e = tid + 512 * i;     // 2048 chunks (128 rows x 16)
        int r = e >> 4;
        int c = e & 15;
        cpasync16(dst + r * PITCH + c * 16, s + (size_t)r * 256 + c * 16);
    }
}

__global__ void __launch_bounds__(512, 1)
inbatch_kernel() {
    extern __shared__ __align__(1024) char smem[];
    __shared__ int s_item;
    const uint32_t sb = smem_to_u32(smem);
    const int tid  = threadIdx.x;
    const int lane = tid & 31;
    const int wid  = tid >> 5;
    const int wm   = wid >> 2;        // 0..3
    const int wn   = wid & 3;         // 0..3

    const uint32_t aOff  = (uint32_t)((wm * 64 + (lane & 15)) * PITCH + (lane & 16));
    const uint32_t bRow  = (uint32_t)(wn * 32 + ((lane >> 4) << 3) + (lane & 7));
    const uint32_t bOffC = (uint32_t)((lane & 8) << 1);
    float* red = (float*)(smem + SMEM_RED);   // [256][4]

    // prologue: pop first item, load its A + B0
    if (tid == 0) s_item = atomicAdd(&g_ctr, 1);
    __syncthreads();
    int cur = s_item;
    int abuf = 0;
    if (cur < NITEMS) {
        load_tileA(sb + SMEM_A0, g_Qh, (cur >> 4) * TILE_M, tid);
        load_tileB(sb + SMEM_B0, g_Dh, ((cur & 15) * CHUNK_TILES) * TILE_N, tid);
        CP_COMMIT();
    }

    while (cur < NITEMS) {
        const int rt = cur >> 4;
        const int cc = cur & 15;
        const int rowBase  = rt * TILE_M;
        const int tileBase = cc * CHUNK_TILES;
        const uint32_t aBase = sb + (abuf ? SMEM_A1 : SMEM_A0) + aOff;

        uint32_t rmax2[4][2];
        #pragma unroll
        for (int mi = 0; mi < 4; ++mi) { rmax2[mi][0] = 0xFC00FC00u; rmax2[mi][1] = 0xFC00FC00u; }

        int nxt = 0;
        for (int j = 0; j < CHUNK_TILES; ++j) {
            CP_WAIT0();
            __syncthreads();
            if (j + 1 < CHUNK_TILES) {
                uint32_t dst = sb + (((j + 1) & 1) ? SMEM_B1 : SMEM_B0);
                load_tileB(dst, g_Dh, (tileBase + j + 1) * TILE_N, tid);
                CP_COMMIT();
                if (j == CHUNK_TILES - 2 && tid == 0) s_item = atomicAdd(&g_ctr, 1);
            } else {
                // last tile: prefetch next item's A + B0 (read s_item, sync'd above)
                nxt = s_item;
                if (nxt < NITEMS) {
                    load_tileA(sb + (abuf ? SMEM_A0 : SMEM_A1), g_Qh, (nxt >> 4) * TILE_M, tid);
                    load_tileB(sb + SMEM_B0, g_Dh, ((nxt & 15) * CHUNK_TILES) * TILE_N, tid);
                    CP_COMMIT();
                }
            }
            const uint32_t bBase = sb + ((j & 1) ? SMEM_B1 : SMEM_B0) + bRow * PITCH + bOffC;

            uint32_t acc[4][4][2];
            #pragma unroll
            for (int mi = 0; mi < 4; ++mi)
                #pragma unroll
                for (int ni = 0; ni < 4; ++ni) { acc[mi][ni][0] = 0u; acc[mi][ni][1] = 0u; }

            #pragma unroll
            for (int ks = 0; ks < 8; ++ks) {
                uint32_t a[4][4];
                #pragma unroll
                for (int mi = 0; mi < 4; ++mi)
                    ldsm4(a[mi], aBase + (uint32_t)(mi * 16 * PITCH + ks * 32));
                uint32_t b[2][4];
                #pragma unroll
                for (int np = 0; np < 2; ++np)
                    ldsm4(b[np], sb * 0 + bBase + (uint32_t)(np * 16 * PITCH + ks * 32));
                #pragma unroll
                for (int mi = 0; mi < 4; ++mi)
                    #pragma unroll
                    for (int ni = 0; ni < 4; ++ni)
                        mma16816h(acc[mi][ni], a[mi],
                                  b[ni >> 1][(ni & 1) * 2], b[ni >> 1][(ni & 1) * 2 + 1]);
            }

            // diagonal handling: global col tile ct hits the diagonal when
            // ct == 2*rt (local rows 0..127) or 2*rt+1 (local rows 128..255)
            const int dt = (tileBase + j) - 2 * rt;
            if (dt == 0 || dt == 1) {
                const int coff = dt * 128;
                #pragma unroll
                for (int mi = 0; mi < 4; ++mi) {
                    int r0 = wm * 64 + mi * 16 + (lane >> 2);
                    #pragma unroll
                    for (int ni = 0; ni < 4; ++ni) {
                        int c0 = wn * 32 + ni * 8 + (lane & 3) * 2 + coff;
                        if (c0     == r0)     acc[mi][ni][0] = (acc[mi][ni][0] & 0xFFFF0000u) | NEGINF_LO;
                        if (c0 + 1 == r0)     acc[mi][ni][0] = (acc[mi][ni][0] & 0x0000FFFFu) | NEGINF_HI;
                        if (c0     == r0 + 8) acc[mi][ni][1] = (acc[mi][ni][1] & 0xFFFF0000u) | NEGINF_LO;
                        if (c0 + 1 == r0 + 8) acc[mi][ni][1] = (acc[mi][ni][1] & 0x0000FFFFu) | NEGINF_HI;
                    }
                }
            }
            #pragma unroll
            for (int mi = 0; mi < 4; ++mi)
                #pragma unroll
                for (int ni = 0; ni < 4; ++ni) {
                    rmax2[mi][0] = hmax2(rmax2[mi][0], acc[mi][ni][0]);
                    rmax2[mi][1] = hmax2(rmax2[mi][1], acc[mi][ni][1]);
                }
        }

        // epilogue (overlaps next item's prefetch): collapse + reduce + atomicMax
        float rmax[8];
        #pragma unroll
        for (int mi = 0; mi < 4; ++mi)
            #pragma unroll
            for (int rr = 0; rr < 2; ++rr) {
                __half2 h = *(__half2*)&rmax2[mi][rr];
                rmax[mi * 2 + rr] = fmaxf(__low2float(h), __high2float(h));
            }
        #pragma unroll
        for (int i = 0; i < 8; ++i) {
            rmax[i] = fmaxf(rmax[i], __shfl_xor_sync(0xFFFFFFFFu, rmax[i], 1));
            rmax[i] = fmaxf(rmax[i], __shfl_xor_sync(0xFFFFFFFFu, rmax[i], 2));
        }
        __syncthreads();
        if ((lane & 3) == 0) {
            #pragma unroll
            for (int mi = 0; mi < 4; ++mi) {
                int rA = wm * 64 + mi * 16 + (lane >> 2);
                red[rA * 4 + wn]       = rmax[mi * 2 + 0];
                red[(rA + 8) * 4 + wn] = rmax[mi * 2 + 1];
            }
        }
        __syncthreads();
        if (tid < TILE_M) {
            float m = fmaxf(fmaxf(red[tid * 4 + 0], red[tid * 4 + 1]),
                            fmaxf(red[tid * 4 + 2], red[tid * 4 + 3]));
            atomicMax(&g_rowmax_enc[rowBase + tid], enc_f(m));
        }

        cur = nxt;
        abuf ^= 1;
    }
}

// ---------------------------------------------------------------------------
// finalize: 64-block deterministic partials + combiner
// ---------------------------------------------------------------------------
__global__ void finalize1_kernel() {
    __shared__ float sm[256];
    int b = blockIdx.x * 256 + threadIdx.x;
    float s = g_term1[b] + softplusf(dec_f(g_rowmax_enc[b]) - g_pos[b]);
    sm[threadIdx.x] = s;
    __syncthreads();
    #pragma unroll
    for (int off = 128; off > 0; off >>= 1) {
        if (threadIdx.x < off) sm[threadIdx.x] += sm[threadIdx.x + off];
        __syncthreads();
    }
    if (threadIdx.x == 0) g_part[blockIdx.x] = sm[0];
}
__global__ void finalize2_kernel(float* __restrict__ out, int B) {
    __shared__ float sm[64];
    sm[threadIdx.x] = g_part[threadIdx.x];
    __syncthreads();
    #pragma unroll
    for (int off = 32; off > 0; off >>= 1) {
        if (threadIdx.x < off) sm[threadIdx.x] += sm[threadIdx.x + off];
        __syncthreads();
    }
    if (threadIdx.x == 0) out[0] = sm[0] / (2.0f * (float)B);
}

// ---------------------------------------------------------------------------
extern "C" void kernel_launch(void* const* d_in, const int* in_sizes, int n_in,
                              void* d_out, int out_size) {
    const float* q  = (const float*)d_in[0];
    const float* dd = (const float*)d_in[1];
    const float* nd = (const float*)d_in[2];
    float* out = (float*)d_out;
    int B = in_sizes[0] / DDIM;   // 16384

    __half *qh = nullptr, *dh = nullptr;
    cudaGetSymbolAddress((void**)&qh, g_Qh);
    cudaGetSymbolAddress((void**)&dh, g_Dh);

    cudaFuncSetAttribute(inbatch_kernel, cudaFuncAttributeMaxDynamicSharedMemorySize, SMEM_TOTAL);

    prep_fused<<<(B * 32) / 256, 256>>>(q, dd, nd, qh, dh);
    inbatch_kernel<<<GRID_PERS, 512, SMEM_TOTAL>>>();
    finalize1_kernel<<<B / 256, 256>>>();   // 64 blocks
    finalize2_kernel<<<1, 64>>>(out, B);
}